// round 4
// baseline (speedup 1.0000x reference)
#include <cuda_runtime.h>
#include <cuda_bf16.h>

// ---------------------------------------------------------------------------
// GuidedAttentionL1Loss — 3 flat streaming launches
//  K1 scan:  zero per-seg sums, prefix-scan lengths -> g_starts, build segof LUT
//  K2 passA: flat float4 stream over attn -> per-seg (Sy,Sxy,Sy2) via warp-
//            grouped atomics;  misc blocks: params L1 + NLL
//  K3 passB: flat float4 stream (L2-resident) -> per-seg (Se,Sye,Se2);
//            last-done block computes D2 per seg + final loss
// No per-block load->barrier->compute phases: memory stays in flight.
// min segment length 1024 >= warp span (1024) => <=2 segment groups per warp.
// ---------------------------------------------------------------------------

#define MAX_B 4096
#define NMISC 148
#define STRIP 32
#define SEGOF_N 8704
#define ALPHA_HALF 5.0e-4
#define BETA_HALF 0.05
#define NEXP2 (-0.72134752044448f)   /* -1/(2 ln 2) */

__device__ double g_psum = 0.0;
__device__ double g_nll  = 0.0;
__device__ int    g_done = 0;
__device__ int    g_starts[MAX_B + 2];
__device__ unsigned short g_segof[SEGOF_N];
__device__ float4 g_sA[MAX_B];   // (Sy, Sxy, Sy2, -)
__device__ float4 g_sB[MAX_B];   // (Se, Sye, Se2, -)

__device__ __forceinline__ bool detect_i64(const void* lengths) {
    // lengths[0] >= 1 always; int64 LE -> high word of element 0 is 0.
    return ((const int*)lengths)[1] == 0;
}
__device__ __forceinline__ int load_int(const void* p, int i, bool is64) {
    return is64 ? (int)((const long long*)p)[i] : ((const int*)p)[i];
}
__device__ __forceinline__ float ex2f(float a) {
    float r;
    asm("ex2.approx.ftz.f32 %0, %1;" : "=f"(r) : "f"(a));
    return r;
}

// Warp-level: reduce (u1,u2,u3) keyed by b (<=2 distinct b per warp) and
// atomically add group totals into dst[b].{x,y,z}. Warp-collective.
__device__ __forceinline__ void group_flush(int b, float u1, float u2, float u3,
                                            float4* dst) {
    const unsigned full = 0xffffffffu;
    int lane = threadIdx.x & 31;
    int b0 = __shfl_sync(full, b, 0);
    bool in0 = (b == b0);
    unsigned m0 = __ballot_sync(full, in0);
    float v1 = in0 ? u1 : 0.0f, v2 = in0 ? u2 : 0.0f, v3 = in0 ? u3 : 0.0f;
#pragma unroll
    for (int o = 16; o > 0; o >>= 1) {
        v1 += __shfl_xor_sync(full, v1, o);
        v2 += __shfl_xor_sync(full, v2, o);
        v3 += __shfl_xor_sync(full, v3, o);
    }
    if (lane == 0) {
        atomicAdd(&dst[b0].x, v1);
        atomicAdd(&dst[b0].y, v2);
        atomicAdd(&dst[b0].z, v3);
    }
    if (m0 != full) {
        int lead = __ffs(~m0) - 1;
        int b1 = __shfl_sync(full, b, lead);
        bool in1 = (b == b1);
        float w1 = in1 ? u1 : 0.0f, w2 = in1 ? u2 : 0.0f, w3 = in1 ? u3 : 0.0f;
#pragma unroll
        for (int o = 16; o > 0; o >>= 1) {
            w1 += __shfl_xor_sync(full, w1, o);
            w2 += __shfl_xor_sync(full, w2, o);
            w3 += __shfl_xor_sync(full, w3, o);
        }
        if (lane == lead) {
            atomicAdd(&dst[b1].x, w1);
            atomicAdd(&dst[b1].y, w2);
            atomicAdd(&dst[b1].z, w3);
        }
    }
}

// Block-reduce two floats (result broadcast not needed; valid at t==0).
__device__ __forceinline__ void block_sum2(float& a, float& b, float (*red)[32]) {
    int lane = threadIdx.x & 31, w = threadIdx.x >> 5;
#pragma unroll
    for (int o = 16; o > 0; o >>= 1) {
        a += __shfl_down_sync(0xffffffffu, a, o);
        b += __shfl_down_sync(0xffffffffu, b, o);
    }
    __syncthreads();
    if (lane == 0) { red[0][w] = a; red[1][w] = b; }
    __syncthreads();
    if (w == 0) {
        int nw = blockDim.x >> 5;
        a = (lane < nw) ? red[0][lane] : 0.0f;
        b = (lane < nw) ? red[1][lane] : 0.0f;
#pragma unroll
        for (int o = 4; o > 0; o >>= 1) {
            a += __shfl_down_sync(0xffffffffu, a, o);
            b += __shfl_down_sync(0xffffffffu, b, o);
        }
    }
}

// ---------------------------------------------------------------------------
// K1: zero sums, prefix-scan lengths, sentinel, segof LUT.
// ---------------------------------------------------------------------------
__global__ __launch_bounds__(1024) void scan_kernel(const void* lengths, int B, int T) {
    __shared__ int wsum[32];
    int t = threadIdx.x, lane = t & 31, w = t >> 5;
    float4 z4 = make_float4(0.f, 0.f, 0.f, 0.f);
    for (int i = t; i < B; i += 1024) { g_sA[i] = z4; g_sB[i] = z4; }
    bool is64 = detect_i64(lengths);

    int l[4];
    int base = t * 4;
#pragma unroll
    for (int j = 0; j < 4; j++)
        l[j] = (base + j < B) ? load_int(lengths, base + j, is64) : 0;
    int tot = l[0] + l[1] + l[2] + l[3];

    int inc = tot;
#pragma unroll
    for (int o = 1; o < 32; o <<= 1) {
        int v = __shfl_up_sync(0xffffffffu, inc, o);
        if (lane >= o) inc += v;
    }
    if (lane == 31) wsum[w] = inc;
    __syncthreads();
    if (w == 0) {
        int v = wsum[lane];
#pragma unroll
        for (int o = 1; o < 32; o <<= 1) {
            int u = __shfl_up_sync(0xffffffffu, v, o);
            if (lane >= o) v += u;
        }
        wsum[lane] = v;
    }
    __syncthreads();
    int warp_base = (w > 0) ? wsum[w - 1] : 0;
    int run = warp_base + inc - tot;      // exclusive prefix
    if (t == 0) g_starts[B] = T;          // sentinel
#pragma unroll
    for (int j = 0; j < 4; j++) {
        if (base + j < B) {
            int s = run, e = run + l[j];
            g_starts[base + j] = s;
            for (int q = (s + 1023) >> 10; q * 1024 < e; q++)
                g_segof[q] = (unsigned short)(base + j);
        }
        run += l[j];
    }
}

// ---------------------------------------------------------------------------
// K2: pass A — flat stream: per-seg (Sy,Sxy,Sy2); misc: L1 + NLL.
// ---------------------------------------------------------------------------
__global__ __launch_bounds__(256) void passA_kernel(
    const float* __restrict__ logits, const float* __restrict__ params,
    const float* __restrict__ attn,
    const void* __restrict__ labels, const void* __restrict__ lengths,
    int P, int B, int T)
{
    int t = threadIdx.x;
    bool is64 = detect_i64(lengths);

    if (blockIdx.x < NMISC) {
        __shared__ float red[2][32];
        int gid = blockIdx.x * 256 + t;
        int stride = NMISC * 256;
        float a = 0.0f;
        const float4* p4 = (const float4*)params;
        int n4 = P >> 2;
        for (int i = gid; i < n4; i += stride) {
            float4 v = p4[i];
            a += fabsf(v.x) + fabsf(v.y) + fabsf(v.z) + fabsf(v.w);
        }
        float nl = 0.0f;
        for (int b = gid; b < B; b += stride) {
            float l0 = logits[2 * b];
            float l1 = logits[2 * b + 1];
            int lab = load_int(labels, b, is64);
            float m = fmaxf(l0, l1);
            float lse = m + logf(expf(l0 - m) + expf(l1 - m));
            nl -= (lab ? l1 : l0) - lse;
        }
        block_sum2(a, nl, red);
        if (t == 0) {
            if (a != 0.0f)  atomicAdd(&g_psum, (double)a);
            if (nl != 0.0f) atomicAdd(&g_nll, (double)nl);
        }
        return;
    }

    int gid = (blockIdx.x - NMISC) * 256 + t;
    int i0 = gid * STRIP;
    int b = B - 1;
    float a1 = 0.f, a2 = 0.f, a3 = 0.f;
    int sb2 = -1;
    float c1 = 0.f, c2 = 0.f, c3 = 0.f;

    if (i0 + STRIP <= T) {
        const float4* yp = (const float4*)(attn + i0);
        float4 v[8];
#pragma unroll
        for (int j = 0; j < 8; j++) v[j] = __ldg(yp + j);

        b = g_segof[i0 >> 10];
        int e = g_starts[b + 1];
        if (i0 >= e) { b++; e = g_starts[b + 1]; }
        int s = g_starts[b];
        int kcross = e - i0;
        float invl = 1.0f / (float)(e - s);
        float xb = (float)(i0 - s) * invl;

        if (kcross >= STRIP) {
#pragma unroll
            for (int j = 0; j < 8; j++) {
                float yy[4] = {v[j].x, v[j].y, v[j].z, v[j].w};
#pragma unroll
                for (int q = 0; q < 4; q++) {
                    float y = yy[q];
                    float x = fmaf((float)(j * 4 + q + 1), invl, xb);
                    a1 += y; a2 = fmaf(x, y, a2); a3 = fmaf(y, y, a3);
                }
            }
        } else {
            int e2 = g_starts[b + 2];
            float invl2 = 1.0f / (float)(e2 - e);
            sb2 = b + 1;
#pragma unroll
            for (int j = 0; j < 8; j++) {
                float yy[4] = {v[j].x, v[j].y, v[j].z, v[j].w};
#pragma unroll
                for (int q = 0; q < 4; q++) {
                    int k = j * 4 + q;
                    float y = yy[q];
                    if (k < kcross) {
                        float x = fmaf((float)(k + 1), invl, xb);
                        a1 += y; a2 = fmaf(x, y, a2); a3 = fmaf(y, y, a3);
                    } else {
                        float x = (float)(k - kcross + 1) * invl2;
                        c1 += y; c2 = fmaf(x, y, c2); c3 = fmaf(y, y, c3);
                    }
                }
            }
        }
    } else if (i0 < T) {
        // partial tail strip (not hit when T % (STRIP*256) == 0)
        int iend = T;
        for (int i = i0; i < iend && i < i0 + STRIP; i++) {
            int bb = g_segof[i >> 10];
            while (i >= g_starts[bb + 1]) bb++;
            int s = g_starts[bb];
            float invl = 1.0f / (float)(g_starts[bb + 1] - s);
            float y = __ldg(&attn[i]);
            float x = (float)(i - s + 1) * invl;
            atomicAdd(&g_sA[bb].x, y);
            atomicAdd(&g_sA[bb].y, x * y);
            atomicAdd(&g_sA[bb].z, y * y);
        }
    }

    group_flush(b, a1, a2, a3, g_sA);
    if (sb2 >= 0) {
        atomicAdd(&g_sA[sb2].x, c1);
        atomicAdd(&g_sA[sb2].y, c2);
        atomicAdd(&g_sA[sb2].z, c3);
    }
}

// ---------------------------------------------------------------------------
// K3: pass B — flat stream (L2-resident): per-seg (Se,Sye,Se2); finalize.
// ---------------------------------------------------------------------------
__global__ __launch_bounds__(256) void passB_kernel(
    const float* __restrict__ attn,
    const void* __restrict__ labels, const void* __restrict__ lengths,
    int B, int T, float* __restrict__ out, int out_size)
{
    int t = threadIdx.x;
    bool is64 = detect_i64(lengths);

    int gid = blockIdx.x * 256 + t;
    int i0 = gid * STRIP;
    int b = B - 1;
    float a1 = 0.f, a2 = 0.f, a3 = 0.f;
    int sb2 = -1;
    float c1 = 0.f, c2 = 0.f, c3 = 0.f;

    if (i0 + STRIP <= T) {
        const float4* yp = (const float4*)(attn + i0);
        float4 v[8];
#pragma unroll
        for (int j = 0; j < 8; j++) v[j] = __ldg(yp + j);

        b = g_segof[i0 >> 10];
        int e = g_starts[b + 1];
        if (i0 >= e) { b++; e = g_starts[b + 1]; }
        int s = g_starts[b];
        int kcross = e - i0;
        float lenf = (float)(e - s);
        float invl = 1.0f / lenf;
        float xb = (float)(i0 - s) * invl;
        float4 sA = g_sA[b];
        float mean = sA.y / sA.x;
        int lab = load_int(labels, b, is64);
        float istd = lab ? lenf : lenf * 1e-3f;
        float m2 = NEXP2 * istd * istd;

        if (kcross >= STRIP) {
#pragma unroll
            for (int j = 0; j < 8; j++) {
                float yy[4] = {v[j].x, v[j].y, v[j].z, v[j].w};
#pragma unroll
                for (int q = 0; q < 4; q++) {
                    float y = yy[q];
                    float x = fmaf((float)(j * 4 + q + 1), invl, xb);
                    float d = x - mean;
                    float ev = ex2f(d * d * m2);
                    a1 += ev; a2 = fmaf(y, ev, a2); a3 = fmaf(ev, ev, a3);
                }
            }
        } else {
            int e2 = g_starts[b + 2];
            float len2 = (float)(e2 - e);
            float invl2 = 1.0f / len2;
            float4 sA2 = g_sA[b + 1];
            float mean2 = sA2.y / sA2.x;
            int lab2 = load_int(labels, b + 1, is64);
            float istd2 = lab2 ? len2 : len2 * 1e-3f;
            float m22 = NEXP2 * istd2 * istd2;
            sb2 = b + 1;
#pragma unroll
            for (int j = 0; j < 8; j++) {
                float yy[4] = {v[j].x, v[j].y, v[j].z, v[j].w};
#pragma unroll
                for (int q = 0; q < 4; q++) {
                    int k = j * 4 + q;
                    float y = yy[q];
                    if (k < kcross) {
                        float x = fmaf((float)(k + 1), invl, xb);
                        float d = x - mean;
                        float ev = ex2f(d * d * m2);
                        a1 += ev; a2 = fmaf(y, ev, a2); a3 = fmaf(ev, ev, a3);
                    } else {
                        float x = (float)(k - kcross + 1) * invl2;
                        float d = x - mean2;
                        float ev = ex2f(d * d * m22);
                        c1 += ev; c2 = fmaf(y, ev, c2); c3 = fmaf(ev, ev, c3);
                    }
                }
            }
        }
    } else if (i0 < T) {
        for (int i = i0; i < T && i < i0 + STRIP; i++) {
            int bb = g_segof[i >> 10];
            while (i >= g_starts[bb + 1]) bb++;
            int s = g_starts[bb];
            float lenf = (float)(g_starts[bb + 1] - s);
            float invl = 1.0f / lenf;
            float4 sA = g_sA[bb];
            float mean = sA.y / sA.x;
            int lab = load_int(labels, bb, is64);
            float istd = lab ? lenf : lenf * 1e-3f;
            float m2 = NEXP2 * istd * istd;
            float y = __ldg(&attn[i]);
            float x = (float)(i - s + 1) * invl;
            float d = x - mean;
            float ev = ex2f(d * d * m2);
            atomicAdd(&g_sB[bb].x, ev);
            atomicAdd(&g_sB[bb].y, y * ev);
            atomicAdd(&g_sB[bb].z, ev * ev);
        }
    }

    group_flush(b, a1, a2, a3, g_sB);
    if (sb2 >= 0) {
        atomicAdd(&g_sB[sb2].x, c1);
        atomicAdd(&g_sB[sb2].y, c2);
        atomicAdd(&g_sB[sb2].z, c3);
    }

    // ---- last-done block: per-seg D2 + final loss ----
    __shared__ bool amlast;
    __threadfence();
    __syncthreads();
    if (t == 0) amlast = (atomicAdd(&g_done, 1) == (int)gridDim.x - 1);
    __syncthreads();
    if (amlast) {
        __shared__ float red[2][32];
        float acc = 0.0f;
        for (int s = t; s < B; s += 256) {
            float4 sA = g_sA[s];
            float4 sB = g_sB[s];
            int len = load_int(lengths, s, is64);
            int lab = load_int(labels, s, is64);
            float lenf = (float)len;
            float istd = lab ? lenf : lenf * 1e-3f;
            float epsp = 2.5066283e-6f / istd;   // 1e-6*sqrt(2pi)/inv_norm-fold
            float rs = 1.0f / (sB.x + epsp);
            float D2 = sA.z - 2.0f * rs * sB.y + rs * rs * sB.z;
            acc += D2 / lenf;
        }
        float dummy = 0.0f;
        block_sum2(acc, dummy, red);
        if (t == 0) {
            double invB = 1.0 / (double)B;
            double nll = g_nll * invB;
            double loss = nll + ALPHA_HALF * g_psum
                        + BETA_HALF * ((double)acc * invB);
            out[0] = (float)loss;
            if (out_size > 1) out[1] = (float)nll;
            g_psum = 0.0; g_nll = 0.0;
            __threadfence();
            g_done = 0;
        }
    }
}

extern "C" void kernel_launch(void* const* d_in, const int* in_sizes, int n_in,
                              void* d_out, int out_size) {
    const float* logits  = (const float*)d_in[0];
    const float* params  = (const float*)d_in[1];
    const float* attn    = (const float*)d_in[2];
    const void*  labels  = d_in[3];
    const void*  lengths = d_in[4];
    // d_in[5] = seg_ids: unused

    int P = in_sizes[1];
    int B = in_sizes[3];
    int T = in_sizes[2];

    int nblk = (T + STRIP * 256 - 1) / (STRIP * 256);

    scan_kernel<<<1, 1024>>>(lengths, B, T);
    passA_kernel<<<NMISC + nblk, 256>>>(logits, params, attn, labels, lengths,
                                        P, B, T);
    passB_kernel<<<nblk, 256>>>(attn, labels, lengths, B, T,
                                (float*)d_out, out_size);
}

// round 5
// speedup vs baseline: 2.6861x; 2.6861x over previous
#include <cuda_runtime.h>
#include <cuda_bf16.h>

// ---------------------------------------------------------------------------
// GuidedAttentionL1Loss — warp-per-segment, barrier-free hot path.
//  K1 scan: prefix-scan lengths -> g_starts (+sentinel)
//  K2 main: blocks [0,NMISC): params L1 + NLL
//           blocks [NMISC,..): 8 warps/block, each warp owns segments
//             b and b+B/2 (paired lengths sum to 2*L_AVG -> perfect balance).
//             pass1: float4 stream -> (Sy,Sxy,Sy2) via warp shuffles
//             pass2: re-read same range (L1/L2-hot) -> (Se,Sye,Se2)
//             label==1: analytic 19-elem Gaussian window instead of full loop
//           last-done block finalizes loss.
// ---------------------------------------------------------------------------

#define MAX_B 4096
#define NMISC 148
#define ALPHA_HALF 5.0e-4
#define BETA_HALF 0.05
#define NEXP2 (-0.72134752044448f)   /* -1/(2 ln 2) */

__device__ double g_psum = 0.0;
__device__ double g_nll  = 0.0;
__device__ double g_attn = 0.0;
__device__ int    g_done = 0;
__device__ int    g_starts[MAX_B + 1];

__device__ __forceinline__ bool detect_i64(const void* lengths) {
    // lengths[0] >= 1 always; int64 LE -> high word of element 0 is 0.
    return ((const int*)lengths)[1] == 0;
}
__device__ __forceinline__ int load_int(const void* p, int i, bool is64) {
    return is64 ? (int)((const long long*)p)[i] : ((const int*)p)[i];
}
__device__ __forceinline__ float ex2f(float a) {
    float r;
    asm("ex2.approx.ftz.f32 %0, %1;" : "=f"(r) : "f"(a));
    return r;
}
__device__ __forceinline__ void warp_sum3(float& a, float& b, float& c) {
    const unsigned full = 0xffffffffu;
#pragma unroll
    for (int o = 16; o > 0; o >>= 1) {
        a += __shfl_xor_sync(full, a, o);
        b += __shfl_xor_sync(full, b, o);
        c += __shfl_xor_sync(full, c, o);
    }
}

// ---------------------------------------------------------------------------
// K1: exclusive prefix scan of lengths -> g_starts, sentinel g_starts[B]=T.
// ---------------------------------------------------------------------------
__global__ __launch_bounds__(1024) void scan_kernel(const void* lengths, int B, int T) {
    __shared__ int wsum[32];
    int t = threadIdx.x, lane = t & 31, w = t >> 5;
    bool is64 = detect_i64(lengths);

    int l[4];
    int base = t * 4;
#pragma unroll
    for (int j = 0; j < 4; j++)
        l[j] = (base + j < B) ? load_int(lengths, base + j, is64) : 0;
    int tot = l[0] + l[1] + l[2] + l[3];

    int inc = tot;
#pragma unroll
    for (int o = 1; o < 32; o <<= 1) {
        int v = __shfl_up_sync(0xffffffffu, inc, o);
        if (lane >= o) inc += v;
    }
    if (lane == 31) wsum[w] = inc;
    __syncthreads();
    if (w == 0) {
        int v = wsum[lane];
#pragma unroll
        for (int o = 1; o < 32; o <<= 1) {
            int u = __shfl_up_sync(0xffffffffu, v, o);
            if (lane >= o) v += u;
        }
        wsum[lane] = v;
    }
    __syncthreads();
    int warp_base = (w > 0) ? wsum[w - 1] : 0;
    int run = warp_base + inc - tot;      // exclusive prefix
    if (t == 0) g_starts[B] = T;
#pragma unroll
    for (int j = 0; j < 4; j++) {
        if (base + j < B) g_starts[base + j] = run;
        run += l[j];
    }
}

// ---------------------------------------------------------------------------
// K2: main.
// ---------------------------------------------------------------------------
__global__ __launch_bounds__(256) void main_kernel(
    const float* __restrict__ logits, const float* __restrict__ params,
    const float* __restrict__ attn,
    const void* __restrict__ labels, const void* __restrict__ lengths,
    int P, int B, float* __restrict__ out, int out_size)
{
    int t = threadIdx.x;
    int lane = t & 31, wid = t >> 5;
    bool is64 = detect_i64(lengths);

    if (blockIdx.x < NMISC) {
        // ----- misc: L1 over params + NLL over logits -----
        __shared__ float red[2][32];
        int gid = blockIdx.x * 256 + t;
        int stride = NMISC * 256;
        float a = 0.0f;
        const float4* p4 = (const float4*)params;
        int n4 = P >> 2;
        for (int i = gid; i < n4; i += stride) {
            float4 v = __ldg(p4 + i);
            a += fabsf(v.x) + fabsf(v.y) + fabsf(v.z) + fabsf(v.w);
        }
        float nl = 0.0f;
        for (int b = gid; b < B; b += stride) {
            float l0 = logits[2 * b];
            float l1 = logits[2 * b + 1];
            int lab = load_int(labels, b, is64);
            float m = fmaxf(l0, l1);
            float lse = m + logf(expf(l0 - m) + expf(l1 - m));
            nl -= (lab ? l1 : l0) - lse;
        }
        // block reduce (a, nl)
#pragma unroll
        for (int o = 16; o > 0; o >>= 1) {
            a  += __shfl_down_sync(0xffffffffu, a, o);
            nl += __shfl_down_sync(0xffffffffu, nl, o);
        }
        if (lane == 0) { red[0][wid] = a; red[1][wid] = nl; }
        __syncthreads();
        if (wid == 0) {
            a  = (lane < 8) ? red[0][lane] : 0.0f;
            nl = (lane < 8) ? red[1][lane] : 0.0f;
#pragma unroll
            for (int o = 4; o > 0; o >>= 1) {
                a  += __shfl_down_sync(0xffffffffu, a, o);
                nl += __shfl_down_sync(0xffffffffu, nl, o);
            }
            if (lane == 0) {
                if (a != 0.0f)  atomicAdd(&g_psum, (double)a);
                if (nl != 0.0f) atomicAdd(&g_nll, (double)nl);
            }
        }
    } else {
        // ----- warp-per-segment, two paired segments per warp -----
        __shared__ float part[8];
        int halfB = B >> 1;
        int wg = (blockIdx.x - NMISC) * 8 + wid;   // 0..halfB-1 (valid)
        float acc = 0.0f;

#pragma unroll 1
        for (int rep = 0; rep < 3; rep++) {
            int b = wg + rep * halfB;
            if (wg >= halfB || b >= B) break;
            if (rep == 2 && 2 * halfB >= B) break;  // only for odd B leftovers

            int s = g_starts[b];
            int len = g_starts[b + 1] - s;
            const float* yp = attn + s;
            float lenf = (float)len;
            float invl = 1.0f / lenf;

            // --- pass 1: Sy, Sxy, Sy2 ---
            int head = (int)((4u - ((unsigned)s & 3u)) & 3u);
            if (head > len) head = len;
            int nb = (len - head) >> 2;           // quads
            int tstart = head + (nb << 2);

            float s1 = 0.f, s2 = 0.f, s3 = 0.f;
            if (lane < head) {
                float y = __ldg(yp + lane);
                float x = (float)(lane + 1) * invl;
                s1 = y; s2 = x * y; s3 = y * y;
            }
            const float4* q4 = (const float4*)(yp + head);
#pragma unroll 4
            for (int i = lane; i < nb; i += 32) {
                float4 v = __ldg(q4 + i);
                float x = (float)(head + (i << 2) + 1) * invl;
                s1 += v.x + v.y + v.z + v.w;
                s2 = fmaf(x, v.x, s2);
                s2 = fmaf(x + invl, v.y, s2);
                s2 = fmaf(x + 2.0f * invl, v.z, s2);
                s2 = fmaf(x + 3.0f * invl, v.w, s2);
                s3 = fmaf(v.x, v.x, s3);
                s3 = fmaf(v.y, v.y, s3);
                s3 = fmaf(v.z, v.z, s3);
                s3 = fmaf(v.w, v.w, s3);
            }
            if (lane < len - tstart) {
                int i = tstart + lane;
                float y = __ldg(yp + i);
                float x = (float)(i + 1) * invl;
                s1 += y; s2 = fmaf(x, y, s2); s3 = fmaf(y, y, s3);
            }
            warp_sum3(s1, s2, s3);
            float mean = s2 / s1;

            int lab = load_int(labels, b, is64);
            float istd = lab ? lenf : lenf * 1e-3f;
            float epsp = 2.5066283e-6f / istd;  // 1e-6*sqrt(2pi)/istd

            // --- pass 2: Se, Sye, Se2 ---
            float s4 = 0.f, s5 = 0.f, s6 = 0.f;
            if (lab) {
                // z = (i+1) - mean*len, spacing 1 -> support |z|<9: <=19 elems
                float c = mean * lenf;
                int i_lo = (int)ceilf(c - 9.0f) - 1;
                if (i_lo < 0) i_lo = 0;
                int i_hi = (int)floorf(c + 9.0f) - 1;
                if (i_hi > len - 1) i_hi = len - 1;
                if (lane <= i_hi - i_lo) {
                    int i = i_lo + lane;
                    float y = __ldg(yp + i);
                    float z = (float)(i + 1) - c;
                    float e = ex2f(NEXP2 * z * z);
                    s4 = e; s5 = y * e; s6 = e * e;
                }
            } else {
                float m2 = NEXP2 * istd * istd;
                if (lane < head) {
                    float y = __ldg(yp + lane);
                    float d = (float)(lane + 1) * invl - mean;
                    float e = ex2f(m2 * d * d);
                    s4 = e; s5 = y * e; s6 = e * e;
                }
#pragma unroll 4
                for (int i = lane; i < nb; i += 32) {
                    float4 v = __ldg(q4 + i);
                    float d = (float)(head + (i << 2) + 1) * invl - mean;
                    float e0 = ex2f(m2 * d * d); d += invl;
                    float e1 = ex2f(m2 * d * d); d += invl;
                    float e2 = ex2f(m2 * d * d); d += invl;
                    float e3 = ex2f(m2 * d * d);
                    s4 += e0 + e1 + e2 + e3;
                    s5 = fmaf(v.x, e0, s5); s5 = fmaf(v.y, e1, s5);
                    s5 = fmaf(v.z, e2, s5); s5 = fmaf(v.w, e3, s5);
                    s6 = fmaf(e0, e0, s6); s6 = fmaf(e1, e1, s6);
                    s6 = fmaf(e2, e2, s6); s6 = fmaf(e3, e3, s6);
                }
                if (lane < len - tstart) {
                    int i = tstart + lane;
                    float y = __ldg(yp + i);
                    float d = (float)(i + 1) * invl - mean;
                    float e = ex2f(m2 * d * d);
                    s4 += e; s5 = fmaf(y, e, s5); s6 = fmaf(e, e, s6);
                }
            }
            warp_sum3(s4, s5, s6);

            float rs = 1.0f / (s4 + epsp);
            float D2 = s3 - 2.0f * rs * s5 + rs * rs * s6;
            acc += D2 * invl;
        }

        if (lane == 0) part[wid] = acc;
        __syncthreads();
        if (t == 0) {
            float sum = 0.0f;
#pragma unroll
            for (int j = 0; j < 8; j++) sum += part[j];
            if (sum != 0.0f) atomicAdd(&g_attn, (double)sum);
        }
    }

    // ----- last-done block finalizes + resets -----
    __threadfence();
    __syncthreads();
    if (t == 0) {
        int prev = atomicAdd(&g_done, 1);
        if (prev == (int)gridDim.x - 1) {
            double invB = 1.0 / (double)B;
            double nll = g_nll * invB;
            double loss = nll + ALPHA_HALF * g_psum + BETA_HALF * (g_attn * invB);
            out[0] = (float)loss;
            if (out_size > 1) out[1] = (float)nll;
            g_psum = 0.0; g_nll = 0.0; g_attn = 0.0;
            __threadfence();
            g_done = 0;
        }
    }
}

extern "C" void kernel_launch(void* const* d_in, const int* in_sizes, int n_in,
                              void* d_out, int out_size) {
    const float* logits  = (const float*)d_in[0];
    const float* params  = (const float*)d_in[1];
    const float* attn    = (const float*)d_in[2];
    const void*  labels  = d_in[3];
    const void*  lengths = d_in[4];
    // d_in[5] = seg_ids: unused

    int P = in_sizes[1];
    int B = in_sizes[3];
    int T = in_sizes[2];

    int halfB = B >> 1;
    int nsegblk = (halfB + 7) >> 3;   // 8 warps/block, 1 seg-pair per warp

    scan_kernel<<<1, 1024>>>(lengths, B, T);
    main_kernel<<<NMISC + nsegblk, 256>>>(logits, params, attn, labels, lengths,
                                          P, B, (float*)d_out, out_size);
}